// round 14
// baseline (speedup 1.0000x reference)
#include <cuda_runtime.h>
#include <cstdint>
#include <math.h>

// Problem constants
#define B_   8
#define T_   4
#define C_   512
#define H_   32
#define W_   32
#define HW_  1024
#define BT_  32          // B_*T_
#define NPART 64         // channel partitions per t
#define CPP   (C_/NPART) // 8 channels per block
#define HP_  28
#define WP_  28
#define NP_  784         // 28*28
#define BN_EPS 1e-5f
#define BSTRIDE ((size_t)T_ * C_ * HW_)   // elements between consecutive b
#define BSTR4   (BSTRIDE/4)               // in float4 units
#define NTHR 512

// Scratch (allocation-free rule: __device__ globals)
__device__ float g_part[NPART][BT_ * HW_];           // 8 MB
__device__ unsigned int       g_maxbits[BT_];        // per-bt max(hm) as bits
__device__ unsigned long long g_minenc[BT_];         // (bits<<32)|idx min-encode
__device__ int                g_cnt[BT_];            // band completion counter

// ---------------------------------------------------------------------------
// Fused kernel (R9 structure): ONE DRAM pass + hot-L2 re-read, plus L2
// prefetch of the next channel issued before the barrier (covers the
// reduction + d^2 dead time with DRAM traffic).
// grid: T_*NPART = 256 blocks (2/SM), 512 threads.
// Also re-initializes the tail's atomic slots every call (first 32 blocks).
// beta cancels exactly in (l_bn - r_bn).
// ---------------------------------------------------------------------------
__global__ __launch_bounds__(NTHR, 2) void fused_kernel(
    const float* __restrict__ l, const float* __restrict__ r,
    const float* __restrict__ gamma)
{
    // init tail atomic slots (visible at kernel boundary)
    if (blockIdx.x < BT_ && threadIdx.x == 0) {
        g_maxbits[blockIdx.x] = 0u;
        g_minenc[blockIdx.x]  = 0xFFFFFFFFFFFFFFFFULL;
        g_cnt[blockIdx.x]     = 0;
    }

    const int t   = blockIdx.x >> 6;        // / NPART
    const int p   = blockIdx.x & (NPART-1);
    const int tid = threadIdx.x;
    const int lane = tid & 31;
    const int wid  = tid >> 5;              // 0..15

    int bvec[4], hw4[4];
    size_t offb[4];
    #pragma unroll
    for (int i = 0; i < 4; i++) {
        const int s = tid + i * NTHR;
        bvec[i] = s >> 8;
        hw4[i]  = s & 255;
        offb[i] = (size_t)bvec[i] * BSTR4 + hw4[i];
    }

    __shared__ float w0[2][16], w1[2][16], w2[2][16], w3[2][16];
    __shared__ float sgamma[CPP];
    if (tid < CPP) sgamma[tid] = gamma[p * CPP + tid];

    float acc[16];
    #pragma unroll
    for (int k = 0; k < 16; k++) acc[k] = 0.f;

    const float4* l4 = reinterpret_cast<const float4*>(l);
    const float4* r4 = reinterpret_cast<const float4*>(r);

    #pragma unroll 1
    for (int ci = 0; ci < CPP; ci++) {
        const int c = p * CPP + ci;
        const size_t chbase = ((size_t)(t * C_ + c)) * (HW_ / 4);

        // ---- stats pass: stream 4+4 float4, accumulate
        float sl = 0.f, ql = 0.f, sr = 0.f, qr = 0.f;
        #pragma unroll
        for (int i = 0; i < 4; i++) {
            float4 lv = l4[offb[i] + chbase];
            float4 rv = r4[offb[i] + chbase];
            sl += (lv.x + lv.y) + (lv.z + lv.w);
            sr += (rv.x + rv.y) + (rv.z + rv.w);
            ql = fmaf(lv.x, lv.x, ql); ql = fmaf(lv.y, lv.y, ql);
            ql = fmaf(lv.z, lv.z, ql); ql = fmaf(lv.w, lv.w, ql);
            qr = fmaf(rv.x, rv.x, qr); qr = fmaf(rv.y, rv.y, qr);
            qr = fmaf(rv.z, rv.z, qr); qr = fmaf(rv.w, rv.w, qr);
        }

        // ---- prefetch next channel to L2 (flies during barrier + d^2)
        if (ci + 1 < CPP) {
            const size_t nb = chbase + (HW_ / 4);
            #pragma unroll
            for (int i = 0; i < 4; i++) {
                asm volatile("prefetch.global.L2 [%0];" :: "l"(l4 + offb[i] + nb));
                asm volatile("prefetch.global.L2 [%0];" :: "l"(r4 + offb[i] + nb));
            }
        }

        // ---- warp shuffle reduction
        #pragma unroll
        for (int o = 16; o > 0; o >>= 1) {
            sl += __shfl_xor_sync(0xffffffffu, sl, o);
            ql += __shfl_xor_sync(0xffffffffu, ql, o);
            sr += __shfl_xor_sync(0xffffffffu, sr, o);
            qr += __shfl_xor_sync(0xffffffffu, qr, o);
        }

        const int par = ci & 1;
        if (lane == 0) {
            w0[par][wid] = sl; w1[par][wid] = ql;
            w2[par][wid] = sr; w3[par][wid] = qr;
        }
        __syncthreads();   // the ONLY barrier per channel

        // ---- every warp combines the 16 warp-sums
        float a0 = (lane < 16) ? w0[par][lane] : 0.f;
        float a1 = (lane < 16) ? w1[par][lane] : 0.f;
        float a2 = (lane < 16) ? w2[par][lane] : 0.f;
        float a3 = (lane < 16) ? w3[par][lane] : 0.f;
        #pragma unroll
        for (int o = 8; o > 0; o >>= 1) {
            a0 += __shfl_xor_sync(0xffffffffu, a0, o);
            a1 += __shfl_xor_sync(0xffffffffu, a1, o);
            a2 += __shfl_xor_sync(0xffffffffu, a2, o);
            a3 += __shfl_xor_sync(0xffffffffu, a3, o);
        }
        a0 = __shfl_sync(0xffffffffu, a0, 0);
        a1 = __shfl_sync(0xffffffffu, a1, 0);
        a2 = __shfl_sync(0xffffffffu, a2, 0);
        a3 = __shfl_sync(0xffffffffu, a3, 0);

        const float inv_n = 1.f / (float)(B_ * HW_);   // 1/8192
        float mul  = a0 * inv_n;
        float mur  = a2 * inv_n;
        float varl = fmaf(-mul, mul, a1 * inv_n);
        float varr = fmaf(-mur, mur, a3 * inv_n);
        float g  = sgamma[ci];
        float A  = g / sqrtf(varl + BN_EPS);
        float Bc = g / sqrtf(varr + BN_EPS);
        float D  = A * mul - Bc * mur;

        // ---- d^2 pass: re-read same data (hot in L2), accumulate
        #pragma unroll
        for (int i = 0; i < 4; i++) {
            float4 lv = l4[offb[i] + chbase];
            float4 rv = r4[offb[i] + chbase];
            float d;
            d = fmaf(A, lv.x, fmaf(-Bc, rv.x, -D)); acc[i*4+0] = fmaf(d, d, acc[i*4+0]);
            d = fmaf(A, lv.y, fmaf(-Bc, rv.y, -D)); acc[i*4+1] = fmaf(d, d, acc[i*4+1]);
            d = fmaf(A, lv.z, fmaf(-Bc, rv.z, -D)); acc[i*4+2] = fmaf(d, d, acc[i*4+2]);
            d = fmaf(A, lv.w, fmaf(-Bc, rv.w, -D)); acc[i*4+3] = fmaf(d, d, acc[i*4+3]);
        }
    }

    // ---- write partials
    float4* gp = reinterpret_cast<float4*>(g_part[p]);
    #pragma unroll
    for (int i = 0; i < 4; i++) {
        gp[(bvec[i] * T_ + t) * (HW_/4) + hw4[i]] =
            make_float4(acc[i*4+0], acc[i*4+1], acc[i*4+2], acc[i*4+3]);
    }
}

// ---------------------------------------------------------------------------
// Window kernel: 128 blocks = (bt x 4 row-bands), 384 threads.
// Band q owns window rows y in [7q, 7q+7); needs d2 rows [7q, 7q+11) (11 rows).
// Phase 1: threads 0..351 sum 64 partials for one (row,col) -> smem band.
// Phase 2: threads 0..195 compute 5x5 window, sqrt, write heatmap slice,
//          track max / min-encoded (bits<<32|idx).
// Phase 3: block reduce; atomics combine bands; last band-block per bt
//          writes value + coords. All values deterministic (atomic max/min
//          over a fixed set; idx tie-break = lowest = JAX first-occurrence).
// Output layout (float32, tuple order):
//   [0,32) values (B,T) | [32,96) coords (B,T,2) [x,y] | [96,25184) heatmap
// ---------------------------------------------------------------------------
__global__ __launch_bounds__(384) void window_kernel(float* __restrict__ out)
{
    const int bt  = blockIdx.x >> 2;
    const int q   = blockIdx.x & 3;
    const int tid = threadIdx.x;
    const int r0  = 7 * q;              // first d2 row of this band

    __shared__ float band[11 * 32];
    __shared__ float smx[256];
    __shared__ unsigned long long smn[256];

    // Phase 1: layer-sum for 352 positions
    if (tid < 352) {
        const int idx = bt * HW_ + (r0 + (tid >> 5)) * W_ + (tid & 31);
        float s0 = 0.f, s1 = 0.f, s2 = 0.f, s3 = 0.f;
        #pragma unroll
        for (int k = 0; k < NPART; k += 4) {
            s0 += g_part[k + 0][idx];
            s1 += g_part[k + 1][idx];
            s2 += g_part[k + 2][idx];
            s3 += g_part[k + 3][idx];
        }
        band[tid] = (s0 + s1) + (s2 + s3);
    }
    __syncthreads();

    // Phase 2: windows
    float mymax = 0.f;                       // hm >= 0 always
    unsigned long long myenc = 0xFFFFFFFFFFFFFFFFULL;
    if (tid < 196) {
        const int wy = tid / 28;             // 0..6 (local)
        const int wx = tid % 28;
        float ws = 0.f;
        #pragma unroll
        for (int dy = 0; dy < 5; dy++)
            #pragma unroll
            for (int dx = 0; dx < 5; dx++)
                ws += band[(wy + dy) * W_ + (wx + dx)];
        const float hm = sqrtf(ws / 25.0f);
        const int gy = r0 + wy;              // global window row
        const int gidx = gy * WP_ + wx;      // flat idx in [0,784)
        out[96 + bt * NP_ + gidx] = hm;
        const unsigned int bits = __float_as_uint(hm);
        mymax = hm;
        myenc = ((unsigned long long)bits << 32) | (unsigned int)gidx;
    }

    // Phase 3: block reduce (pad to 256)
    if (tid < 256) { smx[tid] = mymax; smn[tid] = myenc; }
    __syncthreads();
    for (int st = 128; st > 0; st >>= 1) {
        if (tid < st) {
            smx[tid] = fmaxf(smx[tid], smx[tid + st]);
            if (smn[tid + st] < smn[tid]) smn[tid] = smn[tid + st];
        }
        __syncthreads();
    }

    if (tid == 0) {
        atomicMax(&g_maxbits[bt], __float_as_uint(smx[0]));
        atomicMin(&g_minenc[bt], smn[0]);
        __threadfence();
        const int done = atomicAdd(&g_cnt[bt], 1);
        if (done == 3) {
            // last band for this bt: combine + write scalars
            const unsigned int mb = atomicAdd(&g_maxbits[bt], 0u);
            const unsigned long long me = atomicAdd(&g_minenc[bt], 0ULL);
            const int idx = (int)(me & 0xFFFFFFFFULL);
            out[bt] = __uint_as_float(mb);
            out[32 + bt * 2 + 0] = (float)(idx % WP_);  // x_argmin
            out[32 + bt * 2 + 1] = (float)(idx / WP_);  // y_argmin
        }
    }
}

// ---------------------------------------------------------------------------
extern "C" void kernel_launch(void* const* d_in, const int* in_sizes, int n_in,
                              void* d_out, int out_size)
{
    const float* l     = (const float*)d_in[0];
    const float* r     = (const float*)d_in[1];
    const float* gamma = (const float*)d_in[2];
    // d_in[3] = bn_beta: cancels exactly in (l_bn - r_bn), unused.
    float* out = (float*)d_out;

    fused_kernel<<<T_ * NPART, NTHR>>>(l, r, gamma);
    window_kernel<<<BT_ * 4, 384>>>(out);
}